// round 1
// baseline (speedup 1.0000x reference)
#include <cuda_runtime.h>
#include <cstdint>

// ---------------------------------------------------------------------------
// CorrBlock: corr pyramid via pooled-fmap2 GEMM + bilinear lookup sampler.
//
// Shapes: B=2, C=256, H=W=64, N=8, LEVELS=4, R=4, K=9.
// Levels widths: 64,32,16,8 -> concatenated q dim Q = 4096+1024+256+64 = 5440.
// ---------------------------------------------------------------------------

#define Bb 2
#define Cc 256
#define HH 64
#define WW 64
#define NN 8
#define QTOT 5440
#define PTOT 4096   // H*W

// Scratch (no cudaMalloc allowed): pooled f2 and corr pyramid.
__device__ float g_f2cat[Bb * Cc * QTOT];                    // ~11.1 MB
__device__ float g_corr[(size_t)Bb * PTOT * QTOT];           // ~178 MB

// ---------------------------------------------------------------------------
// Kernel 1: pool fmap2 into 4 levels, concatenated along q.
// grid (C, B), 256 threads.
// ---------------------------------------------------------------------------
__global__ __launch_bounds__(256) void pool_kernel(const float* __restrict__ f2) {
    int c = blockIdx.x, b = blockIdx.y;
    const float* in = f2 + ((size_t)b * Cc + c) * (HH * WW);
    float* outp = g_f2cat + ((size_t)b * Cc + c) * QTOT;

    __shared__ float s0[4096];
    __shared__ float s1[1024];
    __shared__ float s2[256];

    int tid = threadIdx.x;
    // level 0: copy (and stage in smem)
    for (int i = tid; i < 1024; i += 256) {
        float4 v = ((const float4*)in)[i];
        ((float4*)s0)[i] = v;
        ((float4*)outp)[i] = v;  // (b*256+c)*5440*4B is 16B-aligned (5440%4==0)
    }
    __syncthreads();
    // level 1: 32x32
    for (int o = tid; o < 1024; o += 256) {
        int y = o >> 5, x = o & 31;
        float v = 0.25f * (s0[(2*y)*64 + 2*x] + s0[(2*y)*64 + 2*x + 1]
                         + s0[(2*y+1)*64 + 2*x] + s0[(2*y+1)*64 + 2*x + 1]);
        s1[o] = v;
        outp[4096 + o] = v;
    }
    __syncthreads();
    // level 2: 16x16
    if (tid < 256) {
        int y = tid >> 4, x = tid & 15;
        float v = 0.25f * (s1[(2*y)*32 + 2*x] + s1[(2*y)*32 + 2*x + 1]
                         + s1[(2*y+1)*32 + 2*x] + s1[(2*y+1)*32 + 2*x + 1]);
        s2[tid] = v;
        outp[5120 + tid] = v;
    }
    __syncthreads();
    // level 3: 8x8
    if (tid < 64) {
        int y = tid >> 3, x = tid & 7;
        float v = 0.25f * (s2[(2*y)*16 + 2*x] + s2[(2*y)*16 + 2*x + 1]
                         + s2[(2*y+1)*16 + 2*x] + s2[(2*y+1)*16 + 2*x + 1]);
        outp[5376 + tid] = v;
    }
}

// ---------------------------------------------------------------------------
// Packed f32x2 helpers (sm_103a dual-rate fp32 path; ptxas will not auto-fuse)
// ---------------------------------------------------------------------------
__device__ __forceinline__ unsigned long long pk2(float lo, float hi) {
    unsigned long long r;
    asm("mov.b64 %0, {%1, %2};" : "=l"(r) : "f"(lo), "f"(hi));
    return r;
}
__device__ __forceinline__ void upk2(unsigned long long v, float& lo, float& hi) {
    asm("mov.b64 {%0, %1}, %2;" : "=f"(lo), "=f"(hi) : "l"(v));
}
__device__ __forceinline__ void ffma2(unsigned long long& c, unsigned long long a,
                                      unsigned long long b) {
    asm("fma.rn.f32x2 %0, %1, %2, %0;" : "+l"(c) : "l"(a), "l"(b));
}

// ---------------------------------------------------------------------------
// Kernel 2: batched GEMM  corr[b][p][q] = (1/16) * sum_c f1[b][c][p] * f2cat[b][c][q]
// A = f1: [b][k][m] (m contiguous), B = g_f2cat: [b][k][q] (q contiguous).
// Tiles: BM=BN=128, BK=8; 256 threads; 8x8 micro-tile/thread via f32x2.
// grid (ceil(5440/128)=43, 4096/128=32, 2)
// ---------------------------------------------------------------------------
#define BM 128
#define BN 128
#define BK 8

__global__ __launch_bounds__(256) void gemm_kernel(const float* __restrict__ A) {
    __shared__ float As[BK][BM];
    __shared__ float Bs[BK][BN];

    const int b  = blockIdx.z;
    const int m0 = blockIdx.y * BM;
    const int n0 = blockIdx.x * BN;

    const float* Ab = A + (size_t)b * Cc * PTOT;
    const float* Bb_ = g_f2cat + (size_t)b * Cc * QTOT;

    const int tid = threadIdx.x;
    const int lk = tid >> 5;        // 0..7  (k row within slab)
    const int lv = tid & 31;        // 0..31 (float4 column)
    const int ty = tid >> 4;        // 0..15 (micro-tile row group)
    const int tx = tid & 15;        // 0..15 (micro-tile col group)

    unsigned long long acc[8][4];
#pragma unroll
    for (int i = 0; i < 8; i++)
#pragma unroll
        for (int j = 0; j < 4; j++) acc[i][j] = 0ull;

    for (int k0 = 0; k0 < Cc; k0 += BK) {
        float4 av = *(const float4*)(Ab + (size_t)(k0 + lk) * PTOT + m0 + lv * 4);
        float4 bv = make_float4(0.f, 0.f, 0.f, 0.f);
        int q = n0 + lv * 4;
        if (q < QTOT)  // QTOT % 4 == 0, so the whole vec4 is in-range
            bv = *(const float4*)(Bb_ + (size_t)(k0 + lk) * QTOT + q);

        __syncthreads();
        *(float4*)&As[lk][lv * 4] = av;
        *(float4*)&Bs[lk][lv * 4] = bv;
        __syncthreads();

#pragma unroll
        for (int kk = 0; kk < BK; kk++) {
            float4 a0 = *(const float4*)&As[kk][ty * 8];
            float4 a1 = *(const float4*)&As[kk][ty * 8 + 4];
            float4 b0 = *(const float4*)&Bs[kk][tx * 8];
            float4 b1 = *(const float4*)&Bs[kk][tx * 8 + 4];
            unsigned long long bp[4] = {pk2(b0.x, b0.y), pk2(b0.z, b0.w),
                                        pk2(b1.x, b1.y), pk2(b1.z, b1.w)};
            float a[8] = {a0.x, a0.y, a0.z, a0.w, a1.x, a1.y, a1.z, a1.w};
#pragma unroll
            for (int i = 0; i < 8; i++) {
                unsigned long long ap = pk2(a[i], a[i]);
#pragma unroll
                for (int j = 0; j < 4; j++) ffma2(acc[i][j], ap, bp[j]);
            }
        }
    }

    // epilogue: scale by 1/sqrt(256) = 1/16 and store
    const float scale = 0.0625f;
#pragma unroll
    for (int i = 0; i < 8; i++) {
        int m = m0 + ty * 8 + i;
        float* Crow = g_corr + ((size_t)b * PTOT + m) * QTOT;
#pragma unroll
        for (int j = 0; j < 4; j++) {
            int q = n0 + tx * 8 + 2 * j;
            if (q < QTOT) {  // q even, QTOT even -> pair fully in range
                float lo, hi;
                upk2(acc[i][j], lo, hi);
                Crow[q]     = lo * scale;
                Crow[q + 1] = hi * scale;
            }
        }
    }
}

// ---------------------------------------------------------------------------
// Kernel 3: sampler. One block (128 thr) per (b,n,h,w) query; loops 4 levels.
// Per level: cooperatively load the unique <=10x16 patch (guarded float4),
// then 81 threads bilinear-combine and write 81 contiguous outputs.
// Output is the raw row-major (B,N,H,W,324) buffer.
// ---------------------------------------------------------------------------
__global__ __launch_bounds__(128) void sample_kernel(const float* __restrict__ coords,
                                                     float* __restrict__ out) {
    const int idx = blockIdx.x;                  // (((b*8+n)*64+h)*64+w)
    const int w = idx & 63;
    const int h = (idx >> 6) & 63;
    const int n = (idx >> 12) & 7;
    const int b = idx >> 15;
    const int tid = threadIdx.x;

    __shared__ float patch[10][16];

    const float cx = coords[((((size_t)b * NN + n) * 2 + 0) * HH + h) * WW + w];
    const float cy = coords[((((size_t)b * NN + n) * 2 + 1) * HH + h) * WW + w];

    const int p = h * WW + w;
    const float* corrRow = g_corr + ((size_t)b * PTOT + p) * QTOT;
    float* outBase = out + (size_t)idx * 324;

    const int   lvl_off[4] = {0, 4096, 5120, 5376};
    const int   wl[4]      = {64, 32, 16, 8};
    const float inv[4]     = {1.f, 0.5f, 0.25f, 0.125f};

#pragma unroll
    for (int lvl = 0; lvl < 4; lvl++) {
        const int   w2  = wl[lvl];           // h2 == w2
        const float wm1 = (float)(w2 - 1);
        const float cxs = cx * inv[lvl];
        const float cys = cy * inv[lvl];

        const float xlo = fminf(fmaxf(cxs - 4.f, 0.f), wm1);
        const float xhi = fminf(fmaxf(cxs + 4.f, 0.f), wm1);
        const float ylo = fminf(fmaxf(cys - 4.f, 0.f), wm1);
        const float yhi = fminf(fmaxf(cys + 4.f, 0.f), wm1);

        const int xstart = (int)floorf(xlo);
        const int ystart = (int)floorf(ylo);
        const int yend   = min((int)floorf(yhi) + 1, w2 - 1);
        const int xs4    = xstart & ~3;

        const float* lbase = corrRow + lvl_off[lvl];

        if (lvl) __syncthreads();  // prior-level reads done before overwrite
        if (tid < 40) {
            int r = tid >> 2, cb = tid & 3;
            int col = xs4 + cb * 4;
            if (r <= yend - ystart && col < w2) {  // w2 % 4 == 0: vec fully in/out
                float4 v = *(const float4*)(lbase + (ystart + r) * w2 + col);
                *(float4*)&patch[r][cb * 4] = v;
            }
        }
        __syncthreads();

        if (tid < 81) {
            const int ix = tid / 9;          // x-offset index (delta ch0 = d[ix])
            const int iy = tid - ix * 9;     // y-offset index
            float x = fminf(fmaxf(cxs + (float)(ix - 4), 0.f), wm1);
            float y = fminf(fmaxf(cys + (float)(iy - 4), 0.f), wm1);
            float x0f = floorf(x), y0f = floorf(y);
            float fx = x - x0f, fy = y - y0f;
            int x0 = (int)x0f;
            int y0 = (int)y0f;
            int x1 = min(x0 + 1, w2 - 1) - xs4;
            int y1 = min(y0 + 1, w2 - 1) - ystart;
            x0 -= xs4;
            y0 -= ystart;

            float v00 = patch[y0][x0], v01 = patch[y0][x1];
            float v10 = patch[y1][x0], v11 = patch[y1][x1];
            float v = v00 * (1.f - fy) * (1.f - fx)
                    + v01 * (1.f - fy) * fx
                    + v10 * fy * (1.f - fx)
                    + v11 * fy * fx;
            outBase[lvl * 81 + tid] = v;
        }
    }
}

// ---------------------------------------------------------------------------
// Launch
// ---------------------------------------------------------------------------
extern "C" void kernel_launch(void* const* d_in, const int* in_sizes, int n_in,
                              void* d_out, int out_size) {
    const float* f1     = (const float*)d_in[0];
    const float* f2     = (const float*)d_in[1];
    const float* coords = (const float*)d_in[2];
    float* out          = (float*)d_out;

    pool_kernel<<<dim3(Cc, Bb), 256>>>(f2);
    gemm_kernel<<<dim3((QTOT + BN - 1) / BN, PTOT / BM, Bb), 256>>>(f1);
    sample_kernel<<<Bb * NN * HH * WW, 128>>>(coords, out);
}

// round 3
// speedup vs baseline: 2.1826x; 2.1826x over previous
#include <cuda_runtime.h>
#include <cuda_fp16.h>
#include <cstdint>

// ---------------------------------------------------------------------------
// CorrBlock: pooled-fmap2 split-fp16 HMMA (mma.sync) GEMM + bilinear sampler.
// corr = (1/16) * f1^T f2cat, computed as Ahi*Bhi + Ahi*Blo + Alo*Bhi (fp32 acc)
// folded into one GEMM with logical K' = 768.
// (tcgen05 is unavailable: harness compiles at base sm_103.)
// ---------------------------------------------------------------------------

#define Bb 2
#define Cc 256
#define HH 64
#define WW 64
#define NN 8
#define QTOT 5440
#define QPAD 5632      // 22 N-tiles of 256
#define PTOT 4096      // H*W

// Scratch (no cudaMalloc allowed)
__device__ float g_f2cat[Bb * Cc * QTOT];                 // 11.1 MB
__device__ __half g_Ah[(size_t)Bb * PTOT * 512];          // 8.4 MB  [m][hi0..255|lo0..255]
__device__ __half g_Bh[(size_t)Bb * QPAD * 512];          // 11.5 MB [q][hi|lo], zero-padded
__device__ float g_corr[(size_t)Bb * PTOT * QTOT];        // 178 MB

#define SWZ(o) ((o) ^ (((o) >> 3) & 0x70))

__device__ __forceinline__ uint32_t smem_to_u32(const void* p) {
    uint32_t a;
    asm("{ .reg .u64 t; cvta.to.shared.u64 t, %1; cvt.u32.u64 %0, t; }" : "=r"(a) : "l"(p));
    return a;
}
__device__ __forceinline__ void cp_async16(uint32_t dst, const void* src) {
    asm volatile("cp.async.cg.shared.global [%0], [%1], 16;" :: "r"(dst), "l"(src));
}
__device__ __forceinline__ void ldsm_x4(uint32_t* r, uint32_t addr) {
    asm volatile("ldmatrix.sync.aligned.m8n8.x4.shared.b16 {%0,%1,%2,%3}, [%4];"
                 : "=r"(r[0]), "=r"(r[1]), "=r"(r[2]), "=r"(r[3]) : "r"(addr));
}
__device__ __forceinline__ void mma16816(float* d, const uint32_t* a, uint32_t b0, uint32_t b1) {
    asm volatile("mma.sync.aligned.m16n8k16.row.col.f32.f16.f16.f32 "
                 "{%0,%1,%2,%3}, {%4,%5,%6,%7}, {%8,%9}, {%0,%1,%2,%3};"
                 : "+f"(d[0]), "+f"(d[1]), "+f"(d[2]), "+f"(d[3])
                 : "r"(a[0]), "r"(a[1]), "r"(a[2]), "r"(a[3]), "r"(b0), "r"(b1));
}

// ---------------------------------------------------------------------------
// Kernel 1: pool fmap2 into 4 levels, concatenated along q. grid (C, B), 256t.
// ---------------------------------------------------------------------------
__global__ __launch_bounds__(256) void pool_kernel(const float* __restrict__ f2) {
    int c = blockIdx.x, b = blockIdx.y;
    const float* in = f2 + ((size_t)b * Cc + c) * (HH * WW);
    float* outp = g_f2cat + ((size_t)b * Cc + c) * QTOT;
    __shared__ float s0[4096];
    __shared__ float s1[1024];
    __shared__ float s2[256];
    int tid = threadIdx.x;
    for (int i = tid; i < 1024; i += 256) {
        float4 v = ((const float4*)in)[i];
        ((float4*)s0)[i] = v;
        ((float4*)outp)[i] = v;
    }
    __syncthreads();
    for (int o = tid; o < 1024; o += 256) {
        int y = o >> 5, x = o & 31;
        float v = 0.25f * (s0[(2*y)*64 + 2*x] + s0[(2*y)*64 + 2*x + 1]
                         + s0[(2*y+1)*64 + 2*x] + s0[(2*y+1)*64 + 2*x + 1]);
        s1[o] = v; outp[4096 + o] = v;
    }
    __syncthreads();
    if (tid < 256) {
        int y = tid >> 4, x = tid & 15;
        float v = 0.25f * (s1[(2*y)*32 + 2*x] + s1[(2*y)*32 + 2*x + 1]
                         + s1[(2*y+1)*32 + 2*x] + s1[(2*y+1)*32 + 2*x + 1]);
        s2[tid] = v; outp[5120 + tid] = v;
    }
    __syncthreads();
    if (tid < 64) {
        int y = tid >> 3, x = tid & 7;
        float v = 0.25f * (s2[(2*y)*16 + 2*x] + s2[(2*y)*16 + 2*x + 1]
                         + s2[(2*y+1)*16 + 2*x] + s2[(2*y+1)*16 + 2*x + 1]);
        outp[5376 + tid] = v;
    }
}

// ---------------------------------------------------------------------------
// Kernel 2a: transpose f1 [b][c][p] -> fp16 hi/lo [b][p][512]
// ---------------------------------------------------------------------------
__global__ __launch_bounds__(256) void aprep_kernel(const float* __restrict__ f1) {
    __shared__ float tile[32][33];
    int b = blockIdx.z, p0 = blockIdx.x * 32, c0 = blockIdx.y * 32;
    int tx = threadIdx.x, ty = threadIdx.y;
#pragma unroll
    for (int k = 0; k < 4; k++) {
        int c = c0 + ty + 8 * k;
        tile[ty + 8 * k][tx] = f1[((size_t)b * Cc + c) * PTOT + p0 + tx];
    }
    __syncthreads();
#pragma unroll
    for (int k = 0; k < 4; k++) {
        int p = p0 + ty + 8 * k, c = c0 + tx;
        float f = tile[tx][ty + 8 * k];
        __half hi = __float2half_rn(f);
        __half lo = __float2half_rn(f - __half2float(hi));
        size_t base = ((size_t)b * PTOT + p) * 512 + c;
        g_Ah[base] = hi;
        g_Ah[base + 256] = lo;
    }
}

// ---------------------------------------------------------------------------
// Kernel 2b: transpose g_f2cat [b][c][q] -> fp16 hi/lo [b][q][512], pad q>=5440
// ---------------------------------------------------------------------------
__global__ __launch_bounds__(256) void bprep_kernel() {
    __shared__ float tile[32][33];
    int b = blockIdx.z, q0 = blockIdx.x * 32, c0 = blockIdx.y * 32;
    int tx = threadIdx.x, ty = threadIdx.y;
#pragma unroll
    for (int k = 0; k < 4; k++) {
        int c = c0 + ty + 8 * k, q = q0 + tx;
        tile[ty + 8 * k][tx] = (q < QTOT) ? g_f2cat[((size_t)b * Cc + c) * QTOT + q] : 0.f;
    }
    __syncthreads();
#pragma unroll
    for (int k = 0; k < 4; k++) {
        int q = q0 + ty + 8 * k, c = c0 + tx;
        float f = tile[tx][ty + 8 * k];
        __half hi = __float2half_rn(f);
        __half lo = __float2half_rn(f - __half2float(hi));
        size_t base = ((size_t)b * QPAD + q) * 512 + c;
        g_Bh[base] = hi;
        g_Bh[base + 256] = lo;
    }
}

// ---------------------------------------------------------------------------
// Kernel 3: HMMA GEMM. CTA tile 128(M) x 256(N), BK=64 halves, K'=768 (12 chunks),
// 512 threads / 16 warps (warp tile 32x64), cp.async double buffering.
// grid (22, 32, 2).
// ---------------------------------------------------------------------------
#define GT 512
static constexpr int A_BYTES = 128 * 128;        // 128 rows x 128B
static constexpr int B_BYTES = 256 * 128;        // 256 rows x 128B
static constexpr int BUF_B = A_BYTES + B_BYTES;  // 49152
static constexpr int GEMM_SMEM = 2 * BUF_B;      // 98304

__global__ __launch_bounds__(GT, 1) void gemm_kernel() {
    extern __shared__ char smem[];
    const uint32_t sb = smem_to_u32(smem);
    const int tid = threadIdx.x, wid = tid >> 5, lid = tid & 31;
    const int b = blockIdx.z, m0 = blockIdx.y * 128, n0 = blockIdx.x * 256;
    const int warp_m = wid & 3, warp_n = wid >> 2;

    const __half* Ap = g_Ah + (size_t)b * PTOT * 512;
    const __half* Bp = g_Bh + (size_t)b * QPAD * 512;

    float acc[2][8][4];
#pragma unroll
    for (int i = 0; i < 2; i++)
#pragma unroll
        for (int j = 0; j < 8; j++)
#pragma unroll
            for (int k = 0; k < 4; k++) acc[i][j][k] = 0.f;

    // -- async load of one BK=64 chunk into buffer `buf` --
    auto issue_loads = [&](int c, int buf) {
        int sel = c >> 2;                 // 0:HiHi 1:HiLo 2:LoHi
        int kk = (c & 3) * 64;
        int a_off = (sel == 2) ? 256 + kk : kk;
        int b_off = (sel == 1) ? 256 + kk : kk;
        uint32_t aB = sb + buf * BUF_B;
        uint32_t bB = aB + A_BYTES;
#pragma unroll
        for (int i = 0; i < 6; i++) {
            int idx = tid + i * GT;               // 0..3071
            bool isB = idx >= 1024;
            int j = isB ? idx - 1024 : idx;
            int row = j >> 3, c16 = j & 7;
            const __half* src = isB
                ? Bp + (size_t)(n0 + row) * 512 + b_off + c16 * 8
                : Ap + (size_t)(m0 + row) * 512 + a_off + c16 * 8;
            uint32_t dst = (isB ? bB : aB) + SWZ((uint32_t)(row * 128 + c16 * 16));
            cp_async16(dst, src);
        }
        asm volatile("cp.async.commit_group;" ::: "memory");
    };

    issue_loads(0, 0);

    // per-lane ldmatrix address components
    const int a_row = warp_m * 32 + (lid & 15);       // + mb*16
    const int a_kb  = (lid >> 4) * 16;                // k half-block bytes
    const int b_row = warp_n * 64 + ((lid >> 4) & 1) * 8 + (lid & 7);  // + pair*16
    const int b_kb  = ((lid >> 3) & 1) * 16;

    for (int c = 0; c < 12; c++) {
        int buf = c & 1;
        if (c < 11) issue_loads(c + 1, buf ^ 1);
        if (c < 11) asm volatile("cp.async.wait_group 1;" ::: "memory");
        else        asm volatile("cp.async.wait_group 0;" ::: "memory");
        __syncthreads();

        uint32_t aB = sb + buf * BUF_B;
        uint32_t bB = aB + A_BYTES;

#pragma unroll
        for (int ks = 0; ks < 4; ks++) {
            uint32_t af[2][4];
            uint32_t aAddr = aB + SWZ((uint32_t)(a_row * 128 + ks * 32 + a_kb));
            ldsm_x4(af[0], aAddr);
            ldsm_x4(af[1], aAddr + 2048);         // +16 rows (bit11: swizzle-safe)

            uint32_t bf[4][4];
            uint32_t bAddr = bB + SWZ((uint32_t)(b_row * 128 + ks * 32 + b_kb));
#pragma unroll
            for (int p = 0; p < 4; p++) ldsm_x4(bf[p], bAddr + p * 2048);

#pragma unroll
            for (int mb = 0; mb < 2; mb++)
#pragma unroll
                for (int nb = 0; nb < 8; nb++)
                    mma16816(acc[mb][nb], af[mb],
                             bf[nb >> 1][(nb & 1) * 2], bf[nb >> 1][(nb & 1) * 2 + 1]);
        }
        __syncthreads();   // all warps done reading before next overwrite
    }

    // epilogue: scale 1/16, write fp32 corr rows
    const float scale = 0.0625f;
    const int rbase = m0 + warp_m * 32 + (lid >> 2);
    const int cbase = n0 + warp_n * 64 + (lid & 3) * 2;
#pragma unroll
    for (int mb = 0; mb < 2; mb++) {
#pragma unroll
        for (int nb = 0; nb < 8; nb++) {
            int q = cbase + nb * 8;
            if (q < QTOT) {
                int r0 = rbase + mb * 16;
                float* c0p = g_corr + ((size_t)b * PTOT + r0) * QTOT + q;
                float* c1p = c0p + (size_t)8 * QTOT;
                float2 v0 = make_float2(acc[mb][nb][0] * scale, acc[mb][nb][1] * scale);
                float2 v1 = make_float2(acc[mb][nb][2] * scale, acc[mb][nb][3] * scale);
                *(float2*)c0p = v0;
                *(float2*)c1p = v1;
            }
        }
    }
}

// ---------------------------------------------------------------------------
// Kernel 4: sampler (unchanged)
// ---------------------------------------------------------------------------
__global__ __launch_bounds__(128) void sample_kernel(const float* __restrict__ coords,
                                                     float* __restrict__ out) {
    const int idx = blockIdx.x;
    const int w = idx & 63;
    const int h = (idx >> 6) & 63;
    const int n = (idx >> 12) & 7;
    const int b = idx >> 15;
    const int tid = threadIdx.x;

    __shared__ float patch[10][16];

    const float cx = coords[((((size_t)b * NN + n) * 2 + 0) * HH + h) * WW + w];
    const float cy = coords[((((size_t)b * NN + n) * 2 + 1) * HH + h) * WW + w];

    const int p = h * WW + w;
    const float* corrRow = g_corr + ((size_t)b * PTOT + p) * QTOT;
    float* outBase = out + (size_t)idx * 324;

    const int   lvl_off[4] = {0, 4096, 5120, 5376};
    const int   wl[4]      = {64, 32, 16, 8};
    const float inv[4]     = {1.f, 0.5f, 0.25f, 0.125f};

#pragma unroll
    for (int lvl = 0; lvl < 4; lvl++) {
        const int   w2  = wl[lvl];
        const float wm1 = (float)(w2 - 1);
        const float cxs = cx * inv[lvl];
        const float cys = cy * inv[lvl];

        const float ylo = fminf(fmaxf(cys - 4.f, 0.f), wm1);
        const float yhi = fminf(fmaxf(cys + 4.f, 0.f), wm1);
        const float xlo = fminf(fmaxf(cxs - 4.f, 0.f), wm1);

        const int xstart = (int)floorf(xlo);
        const int ystart = (int)floorf(ylo);
        const int yend   = min((int)floorf(yhi) + 1, w2 - 1);
        const int xs4    = xstart & ~3;

        const float* lbase = corrRow + lvl_off[lvl];

        if (lvl) __syncthreads();
        if (tid < 40) {
            int r = tid >> 2, cb = tid & 3;
            int col = xs4 + cb * 4;
            if (r <= yend - ystart && col < w2) {
                float4 v = *(const float4*)(lbase + (ystart + r) * w2 + col);
                *(float4*)&patch[r][cb * 4] = v;
            }
        }
        __syncthreads();

        if (tid < 81) {
            const int ix = tid / 9;
            const int iy = tid - ix * 9;
            float x = fminf(fmaxf(cxs + (float)(ix - 4), 0.f), wm1);
            float y = fminf(fmaxf(cys + (float)(iy - 4), 0.f), wm1);
            float x0f = floorf(x), y0f = floorf(y);
            float fx = x - x0f, fy = y - y0f;
            int x0 = (int)x0f;
            int y0 = (int)y0f;
            int x1 = min(x0 + 1, w2 - 1) - xs4;
            int y1 = min(y0 + 1, w2 - 1) - ystart;
            x0 -= xs4;
            y0 -= ystart;

            float v00 = patch[y0][x0], v01 = patch[y0][x1];
            float v10 = patch[y1][x0], v11 = patch[y1][x1];
            float v = v00 * (1.f - fy) * (1.f - fx)
                    + v01 * (1.f - fy) * fx
                    + v10 * fy * (1.f - fx)
                    + v11 * fy * fx;
            outBase[lvl * 81 + tid] = v;
        }
    }
}

// ---------------------------------------------------------------------------
// Launch
// ---------------------------------------------------------------------------
extern "C" void kernel_launch(void* const* d_in, const int* in_sizes, int n_in,
                              void* d_out, int out_size) {
    const float* f1     = (const float*)d_in[0];
    const float* f2     = (const float*)d_in[1];
    const float* coords = (const float*)d_in[2];
    float* out          = (float*)d_out;

    pool_kernel<<<dim3(Cc, Bb), 256>>>(f2);
    aprep_kernel<<<dim3(PTOT / 32, Cc / 32, Bb), dim3(32, 8)>>>(f1);
    bprep_kernel<<<dim3(QPAD / 32, Cc / 32, Bb), dim3(32, 8)>>>();

    cudaFuncSetAttribute(gemm_kernel, cudaFuncAttributeMaxDynamicSharedMemorySize, GEMM_SMEM);
    gemm_kernel<<<dim3(QPAD / 256, PTOT / 128, Bb), GT, GEMM_SMEM>>>();

    sample_kernel<<<Bb * NN * HH * WW, 128>>>(coords, out);
}

// round 4
// speedup vs baseline: 2.9382x; 1.3462x over previous
#include <cuda_runtime.h>
#include <cuda_fp16.h>
#include <cstdint>

// ---------------------------------------------------------------------------
// CorrBlock: pooled-fmap2 split-fp16 HMMA GEMM (2-pass: A*Bhi) + warp sampler.
// corr = (1/16) * f1^T f2cat  ≈ (1/16) * (Ahi*Bhi + Alo*Bhi), fp32 accumulate.
// Dropped A*Blo term => rel err ~2e-4 (threshold 1e-3).
// ---------------------------------------------------------------------------

#define Bb 2
#define Cc 256
#define HH 64
#define WW 64
#define NN 8
#define QTOT 5440
#define QPAD 5632      // 22 N-tiles of 256
#define PTOT 4096      // H*W

// Scratch (no cudaMalloc allowed)
__device__ float g_f2cat[Bb * Cc * QTOT];                 // 11.1 MB
__device__ __half g_Ah[(size_t)Bb * PTOT * 512];          // 8.4 MB  [m][hi0..255|lo0..255]
__device__ __half g_Bh[(size_t)Bb * QPAD * 256];          // 5.7 MB  [q][hi], zero-padded
__device__ float g_corr[(size_t)Bb * PTOT * QTOT];        // 178 MB

#define SWZ(o) ((o) ^ (((o) >> 3) & 0x70))

__device__ __forceinline__ uint32_t smem_to_u32(const void* p) {
    uint32_t a;
    asm("{ .reg .u64 t; cvta.to.shared.u64 t, %1; cvt.u32.u64 %0, t; }" : "=r"(a) : "l"(p));
    return a;
}
__device__ __forceinline__ void cp_async16(uint32_t dst, const void* src) {
    asm volatile("cp.async.cg.shared.global [%0], [%1], 16;" :: "r"(dst), "l"(src));
}
__device__ __forceinline__ void ldsm_x4(uint32_t* r, uint32_t addr) {
    asm volatile("ldmatrix.sync.aligned.m8n8.x4.shared.b16 {%0,%1,%2,%3}, [%4];"
                 : "=r"(r[0]), "=r"(r[1]), "=r"(r[2]), "=r"(r[3]) : "r"(addr));
}
__device__ __forceinline__ void mma16816(float* d, const uint32_t* a, uint32_t b0, uint32_t b1) {
    asm volatile("mma.sync.aligned.m16n8k16.row.col.f32.f16.f16.f32 "
                 "{%0,%1,%2,%3}, {%4,%5,%6,%7}, {%8,%9}, {%0,%1,%2,%3};"
                 : "+f"(d[0]), "+f"(d[1]), "+f"(d[2]), "+f"(d[3])
                 : "r"(a[0]), "r"(a[1]), "r"(a[2]), "r"(a[3]), "r"(b0), "r"(b1));
}

// ---------------------------------------------------------------------------
// Kernel 1: pool fmap2 into 4 levels, concatenated along q. grid (C, B), 256t.
// ---------------------------------------------------------------------------
__global__ __launch_bounds__(256) void pool_kernel(const float* __restrict__ f2) {
    int c = blockIdx.x, b = blockIdx.y;
    const float* in = f2 + ((size_t)b * Cc + c) * (HH * WW);
    float* outp = g_f2cat + ((size_t)b * Cc + c) * QTOT;
    __shared__ float s0[4096];
    __shared__ float s1[1024];
    __shared__ float s2[256];
    int tid = threadIdx.x;
    for (int i = tid; i < 1024; i += 256) {
        float4 v = ((const float4*)in)[i];
        ((float4*)s0)[i] = v;
        ((float4*)outp)[i] = v;
    }
    __syncthreads();
    for (int o = tid; o < 1024; o += 256) {
        int y = o >> 5, x = o & 31;
        float v = 0.25f * (s0[(2*y)*64 + 2*x] + s0[(2*y)*64 + 2*x + 1]
                         + s0[(2*y+1)*64 + 2*x] + s0[(2*y+1)*64 + 2*x + 1]);
        s1[o] = v; outp[4096 + o] = v;
    }
    __syncthreads();
    if (tid < 256) {
        int y = tid >> 4, x = tid & 15;
        float v = 0.25f * (s1[(2*y)*32 + 2*x] + s1[(2*y)*32 + 2*x + 1]
                         + s1[(2*y+1)*32 + 2*x] + s1[(2*y+1)*32 + 2*x + 1]);
        s2[tid] = v; outp[5120 + tid] = v;
    }
    __syncthreads();
    if (tid < 64) {
        int y = tid >> 3, x = tid & 7;
        float v = 0.25f * (s2[(2*y)*16 + 2*x] + s2[(2*y)*16 + 2*x + 1]
                         + s2[(2*y+1)*16 + 2*x] + s2[(2*y+1)*16 + 2*x + 1]);
        outp[5376 + tid] = v;
    }
}

// ---------------------------------------------------------------------------
// Kernel 2a: transpose f1 [b][c][p] -> fp16 hi/lo [b][p][512]
// ---------------------------------------------------------------------------
__global__ __launch_bounds__(256) void aprep_kernel(const float* __restrict__ f1) {
    __shared__ float tile[32][33];
    int b = blockIdx.z, p0 = blockIdx.x * 32, c0 = blockIdx.y * 32;
    int tx = threadIdx.x, ty = threadIdx.y;
#pragma unroll
    for (int k = 0; k < 4; k++) {
        int c = c0 + ty + 8 * k;
        tile[ty + 8 * k][tx] = f1[((size_t)b * Cc + c) * PTOT + p0 + tx];
    }
    __syncthreads();
#pragma unroll
    for (int k = 0; k < 4; k++) {
        int p = p0 + ty + 8 * k, c = c0 + tx;
        float f = tile[tx][ty + 8 * k];
        __half hi = __float2half_rn(f);
        __half lo = __float2half_rn(f - __half2float(hi));
        size_t base = ((size_t)b * PTOT + p) * 512 + c;
        g_Ah[base] = hi;
        g_Ah[base + 256] = lo;
    }
}

// ---------------------------------------------------------------------------
// Kernel 2b: transpose g_f2cat [b][c][q] -> fp16 hi [b][q][256], pad q>=5440
// ---------------------------------------------------------------------------
__global__ __launch_bounds__(256) void bprep_kernel() {
    __shared__ float tile[32][33];
    int b = blockIdx.z, q0 = blockIdx.x * 32, c0 = blockIdx.y * 32;
    int tx = threadIdx.x, ty = threadIdx.y;
#pragma unroll
    for (int k = 0; k < 4; k++) {
        int c = c0 + ty + 8 * k, q = q0 + tx;
        tile[ty + 8 * k][tx] = (q < QTOT) ? g_f2cat[((size_t)b * Cc + c) * QTOT + q] : 0.f;
    }
    __syncthreads();
#pragma unroll
    for (int k = 0; k < 4; k++) {
        int q = q0 + ty + 8 * k, c = c0 + tx;
        g_Bh[((size_t)b * QPAD + q) * 256 + c] = __float2half_rn(tile[tx][ty + 8 * k]);
    }
}

// ---------------------------------------------------------------------------
// Kernel 3: HMMA GEMM. CTA tile 128(M) x 256(N), BK=64 halves, K'=512 (8 chunks:
// Ahi*Bhi then Alo*Bhi), 512 threads / 16 warps (warp tile 32x64),
// 3-stage cp.async pipeline. grid (22, 32, 2).
// ---------------------------------------------------------------------------
#define GT 512
static constexpr int A_BYTES = 128 * 128;        // 128 rows x 128B
static constexpr int B_BYTES = 256 * 128;        // 256 rows x 128B
static constexpr int BUF_B = A_BYTES + B_BYTES;  // 49152
static constexpr int GEMM_SMEM = 3 * BUF_B;      // 147456

__global__ __launch_bounds__(GT, 1) void gemm_kernel() {
    extern __shared__ char smem[];
    const uint32_t sb = smem_to_u32(smem);
    const int tid = threadIdx.x, wid = tid >> 5, lid = tid & 31;
    const int b = blockIdx.z, m0 = blockIdx.y * 128, n0 = blockIdx.x * 256;
    const int warp_m = wid & 3, warp_n = wid >> 2;

    const __half* Ap = g_Ah + (size_t)b * PTOT * 512;
    const __half* Bp = g_Bh + (size_t)b * QPAD * 256;

    float acc[2][8][4];
#pragma unroll
    for (int i = 0; i < 2; i++)
#pragma unroll
        for (int j = 0; j < 8; j++)
#pragma unroll
            for (int k = 0; k < 4; k++) acc[i][j][k] = 0.f;

    // -- async load of chunk c (c: 0..7; A k-offset c*64, B k-offset (c&3)*64) --
    auto issue_loads = [&](int c, int buf) {
        int a_off = c * 64;
        int b_off = (c & 3) * 64;
        uint32_t aB = sb + buf * BUF_B;
        uint32_t bB = aB + A_BYTES;
#pragma unroll
        for (int i = 0; i < 6; i++) {
            int idx = tid + i * GT;               // 0..3071
            bool isB = idx >= 1024;
            int j = isB ? idx - 1024 : idx;
            int row = j >> 3, c16 = j & 7;
            const __half* src = isB
                ? Bp + (size_t)(n0 + row) * 256 + b_off + c16 * 8
                : Ap + (size_t)(m0 + row) * 512 + a_off + c16 * 8;
            uint32_t dst = (isB ? bB : aB) + SWZ((uint32_t)(row * 128 + c16 * 16));
            cp_async16(dst, src);
        }
        asm volatile("cp.async.commit_group;" ::: "memory");
    };

    issue_loads(0, 0);
    issue_loads(1, 1);

    // per-lane ldmatrix address components
    const int a_row = warp_m * 32 + (lid & 15);
    const int a_kb  = (lid >> 4) * 16;
    const int b_row = warp_n * 64 + ((lid >> 4) & 1) * 8 + (lid & 7);
    const int b_kb  = ((lid >> 3) & 1) * 16;

    for (int c = 0; c < 8; c++) {
        int buf = c % 3;
        if (c < 6) {
            issue_loads(c + 2, (c + 2) % 3);
            asm volatile("cp.async.wait_group 2;" ::: "memory");
        } else if (c == 6) {
            asm volatile("cp.async.wait_group 1;" ::: "memory");
        } else {
            asm volatile("cp.async.wait_group 0;" ::: "memory");
        }
        __syncthreads();

        uint32_t aB = sb + buf * BUF_B;
        uint32_t bB = aB + A_BYTES;

#pragma unroll
        for (int ks = 0; ks < 4; ks++) {
            uint32_t af[2][4];
            uint32_t aAddr = aB + SWZ((uint32_t)(a_row * 128 + ks * 32 + a_kb));
            ldsm_x4(af[0], aAddr);
            ldsm_x4(af[1], aAddr + 2048);

            uint32_t bf[4][4];
            uint32_t bAddr = bB + SWZ((uint32_t)(b_row * 128 + ks * 32 + b_kb));
#pragma unroll
            for (int p = 0; p < 4; p++) ldsm_x4(bf[p], bAddr + p * 2048);

#pragma unroll
            for (int mb = 0; mb < 2; mb++)
#pragma unroll
                for (int nb = 0; nb < 8; nb++)
                    mma16816(acc[mb][nb], af[mb],
                             bf[nb >> 1][(nb & 1) * 2], bf[nb >> 1][(nb & 1) * 2 + 1]);
        }
        __syncthreads();   // all warps done reading before this buffer is refilled
    }

    // epilogue: scale 1/16, write fp32 corr rows
    const float scale = 0.0625f;
    const int rbase = m0 + warp_m * 32 + (lid >> 2);
    const int cbase = n0 + warp_n * 64 + (lid & 3) * 2;
#pragma unroll
    for (int mb = 0; mb < 2; mb++) {
#pragma unroll
        for (int nb = 0; nb < 8; nb++) {
            int q = cbase + nb * 8;
            if (q < QTOT) {
                int r0 = rbase + mb * 16;
                float* c0p = g_corr + ((size_t)b * PTOT + r0) * QTOT + q;
                float* c1p = c0p + (size_t)8 * QTOT;
                float2 v0 = make_float2(acc[mb][nb][0] * scale, acc[mb][nb][1] * scale);
                float2 v1 = make_float2(acc[mb][nb][2] * scale, acc[mb][nb][3] * scale);
                *(float2*)c0p = v0;
                *(float2*)c1p = v1;
            }
        }
    }
}

// ---------------------------------------------------------------------------
// Kernel 4: sampler, warp-per-query. 128 threads = 4 warps = 4 queries.
// Per level: warp loads <=10x16 patch (guarded float4), 81 bilinear outputs.
// grid 16384.
// ---------------------------------------------------------------------------
__global__ __launch_bounds__(128) void sample_kernel(const float* __restrict__ coords,
                                                     float* __restrict__ out) {
    const int warp = threadIdx.x >> 5;
    const int lane = threadIdx.x & 31;
    const int qid = blockIdx.x * 4 + warp;      // (((b*8+n)*64+h)*64+w)
    const int w = qid & 63;
    const int h = (qid >> 6) & 63;
    const int n = (qid >> 12) & 7;
    const int b = qid >> 15;

    __shared__ float patch[4][10][16];
    float (*pp)[16] = patch[warp];

    const float cx = coords[((((size_t)b * NN + n) * 2 + 0) * HH + h) * WW + w];
    const float cy = coords[((((size_t)b * NN + n) * 2 + 1) * HH + h) * WW + w];

    const int p = h * WW + w;
    const float* corrRow = g_corr + ((size_t)b * PTOT + p) * QTOT;
    float* outBase = out + (size_t)qid * 324;

    const int   lvl_off[4] = {0, 4096, 5120, 5376};
    const int   wl[4]      = {64, 32, 16, 8};
    const float inv[4]     = {1.f, 0.5f, 0.25f, 0.125f};

#pragma unroll
    for (int lvl = 0; lvl < 4; lvl++) {
        const int   w2  = wl[lvl];
        const float wm1 = (float)(w2 - 1);
        const float cxs = cx * inv[lvl];
        const float cys = cy * inv[lvl];

        const float ylo = fminf(fmaxf(cys - 4.f, 0.f), wm1);
        const float yhi = fminf(fmaxf(cys + 4.f, 0.f), wm1);
        const float xlo = fminf(fmaxf(cxs - 4.f, 0.f), wm1);

        const int xstart = (int)floorf(xlo);
        const int ystart = (int)floorf(ylo);
        const int yend   = min((int)floorf(yhi) + 1, w2 - 1);
        const int xs4    = xstart & ~3;

        const float* lbase = corrRow + lvl_off[lvl];

        if (lvl) __syncwarp();   // previous level's reads done before overwrite
        // 40 float4 slots over 32 lanes (slot = lane and lane+32)
#pragma unroll
        for (int s = 0; s < 2; s++) {
            int slot = lane + s * 32;
            if (slot < 40) {
                int r = slot >> 2, cb = slot & 3;
                int col = xs4 + cb * 4;
                if (r <= yend - ystart && col < w2) {
                    float4 v = *(const float4*)(lbase + (ystart + r) * w2 + col);
                    *(float4*)&pp[r][cb * 4] = v;
                }
            }
        }
        __syncwarp();

#pragma unroll
        for (int s = 0; s < 3; s++) {
            int t = lane + s * 32;
            if (t < 81) {
                const int ix = t / 9;
                const int iy = t - ix * 9;
                float x = fminf(fmaxf(cxs + (float)(ix - 4), 0.f), wm1);
                float y = fminf(fmaxf(cys + (float)(iy - 4), 0.f), wm1);
                float x0f = floorf(x), y0f = floorf(y);
                float fx = x - x0f, fy = y - y0f;
                int x0 = (int)x0f;
                int y0 = (int)y0f;
                int x1 = min(x0 + 1, w2 - 1) - xs4;
                int y1 = min(y0 + 1, w2 - 1) - ystart;
                x0 -= xs4;
                y0 -= ystart;

                float v00 = pp[y0][x0], v01 = pp[y0][x1];
                float v10 = pp[y1][x0], v11 = pp[y1][x1];
                float v = v00 * (1.f - fy) * (1.f - fx)
                        + v01 * (1.f - fy) * fx
                        + v10 * fy * (1.f - fx)
                        + v11 * fy * fx;
                outBase[lvl * 81 + t] = v;
            }
        }
    }
}

// ---------------------------------------------------------------------------
// Launch
// ---------------------------------------------------------------------------
extern "C" void kernel_launch(void* const* d_in, const int* in_sizes, int n_in,
                              void* d_out, int out_size) {
    const float* f1     = (const float*)d_in[0];
    const float* f2     = (const float*)d_in[1];
    const float* coords = (const float*)d_in[2];
    float* out          = (float*)d_out;

    pool_kernel<<<dim3(Cc, Bb), 256>>>(f2);
    aprep_kernel<<<dim3(PTOT / 32, Cc / 32, Bb), dim3(32, 8)>>>(f1);
    bprep_kernel<<<dim3(QPAD / 32, Cc / 32, Bb), dim3(32, 8)>>>();

    cudaFuncSetAttribute(gemm_kernel, cudaFuncAttributeMaxDynamicSharedMemorySize, GEMM_SMEM);
    gemm_kernel<<<dim3(QPAD / 256, PTOT / 128, Bb), GT, GEMM_SMEM>>>();

    sample_kernel<<<Bb * NN * HH * WW / 4, 128>>>(coords, out);
}

// round 5
// speedup vs baseline: 3.0761x; 1.0469x over previous
#include <cuda_runtime.h>
#include <cuda_fp16.h>
#include <cstdint>

// ---------------------------------------------------------------------------
// CorrBlock: pooled-fmap2 split-fp16 HMMA GEMM (2-pass: A*Bhi) + warp sampler.
// corr = (1/16) * f1^T f2cat ≈ (1/16)(Ahi*Bhi + Alo*Bhi), fp32 acc, fp16 store.
// GEMM: CTA 128x256, 8 warps @ 64x64 warp tile, 3-stage cp.async, 1 sync/chunk.
// ---------------------------------------------------------------------------

#define Bb 2
#define Cc 256
#define HH 64
#define WW 64
#define NN 8
#define QTOT 5440
#define QPAD 5632      // 22 N-tiles of 256
#define PTOT 4096      // H*W

// Scratch (no cudaMalloc allowed)
__device__ float g_f2cat[Bb * Cc * QTOT];                 // 11.1 MB
__device__ __half g_Ah[(size_t)Bb * PTOT * 512];          // 8.4 MB  [m][hi|lo]
__device__ __half g_Bh[(size_t)Bb * QPAD * 256];          // 5.7 MB  [q][hi]
__device__ __half g_corrh[(size_t)Bb * PTOT * QTOT];      // 89 MB   fp16 corr

#define SWZ(o) ((o) ^ (((o) >> 3) & 0x70))

__device__ __forceinline__ uint32_t smem_to_u32(const void* p) {
    uint32_t a;
    asm("{ .reg .u64 t; cvta.to.shared.u64 t, %1; cvt.u32.u64 %0, t; }" : "=r"(a) : "l"(p));
    return a;
}
__device__ __forceinline__ void cp_async16(uint32_t dst, const void* src) {
    asm volatile("cp.async.cg.shared.global [%0], [%1], 16;" :: "r"(dst), "l"(src));
}
__device__ __forceinline__ void ldsm_x4(uint32_t* r, uint32_t addr) {
    asm volatile("ldmatrix.sync.aligned.m8n8.x4.shared.b16 {%0,%1,%2,%3}, [%4];"
                 : "=r"(r[0]), "=r"(r[1]), "=r"(r[2]), "=r"(r[3]) : "r"(addr));
}
__device__ __forceinline__ void mma16816(float* d, const uint32_t* a, uint32_t b0, uint32_t b1) {
    asm volatile("mma.sync.aligned.m16n8k16.row.col.f32.f16.f16.f32 "
                 "{%0,%1,%2,%3}, {%4,%5,%6,%7}, {%8,%9}, {%0,%1,%2,%3};"
                 : "+f"(d[0]), "+f"(d[1]), "+f"(d[2]), "+f"(d[3])
                 : "r"(a[0]), "r"(a[1]), "r"(a[2]), "r"(a[3]), "r"(b0), "r"(b1));
}

// ---------------------------------------------------------------------------
// Kernel 1: pool fmap2 into 4 levels, concatenated along q. grid (C, B), 256t.
// ---------------------------------------------------------------------------
__global__ __launch_bounds__(256) void pool_kernel(const float* __restrict__ f2) {
    int c = blockIdx.x, b = blockIdx.y;
    const float* in = f2 + ((size_t)b * Cc + c) * (HH * WW);
    float* outp = g_f2cat + ((size_t)b * Cc + c) * QTOT;
    __shared__ float s0[4096];
    __shared__ float s1[1024];
    __shared__ float s2[256];
    int tid = threadIdx.x;
    for (int i = tid; i < 1024; i += 256) {
        float4 v = ((const float4*)in)[i];
        ((float4*)s0)[i] = v;
        ((float4*)outp)[i] = v;
    }
    __syncthreads();
    for (int o = tid; o < 1024; o += 256) {
        int y = o >> 5, x = o & 31;
        float v = 0.25f * (s0[(2*y)*64 + 2*x] + s0[(2*y)*64 + 2*x + 1]
                         + s0[(2*y+1)*64 + 2*x] + s0[(2*y+1)*64 + 2*x + 1]);
        s1[o] = v; outp[4096 + o] = v;
    }
    __syncthreads();
    if (tid < 256) {
        int y = tid >> 4, x = tid & 15;
        float v = 0.25f * (s1[(2*y)*32 + 2*x] + s1[(2*y)*32 + 2*x + 1]
                         + s1[(2*y+1)*32 + 2*x] + s1[(2*y+1)*32 + 2*x + 1]);
        s2[tid] = v; outp[5120 + tid] = v;
    }
    __syncthreads();
    if (tid < 64) {
        int y = tid >> 3, x = tid & 7;
        float v = 0.25f * (s2[(2*y)*16 + 2*x] + s2[(2*y)*16 + 2*x + 1]
                         + s2[(2*y+1)*16 + 2*x] + s2[(2*y+1)*16 + 2*x + 1]);
        outp[5376 + tid] = v;
    }
}

// ---------------------------------------------------------------------------
// Kernel 2a: transpose f1 [b][c][p] -> fp16 hi/lo [b][p][512]
// ---------------------------------------------------------------------------
__global__ __launch_bounds__(256) void aprep_kernel(const float* __restrict__ f1) {
    __shared__ float tile[32][33];
    int b = blockIdx.z, p0 = blockIdx.x * 32, c0 = blockIdx.y * 32;
    int tx = threadIdx.x, ty = threadIdx.y;
#pragma unroll
    for (int k = 0; k < 4; k++) {
        int c = c0 + ty + 8 * k;
        tile[ty + 8 * k][tx] = f1[((size_t)b * Cc + c) * PTOT + p0 + tx];
    }
    __syncthreads();
#pragma unroll
    for (int k = 0; k < 4; k++) {
        int p = p0 + ty + 8 * k, c = c0 + tx;
        float f = tile[tx][ty + 8 * k];
        __half hi = __float2half_rn(f);
        __half lo = __float2half_rn(f - __half2float(hi));
        size_t base = ((size_t)b * PTOT + p) * 512 + c;
        g_Ah[base] = hi;
        g_Ah[base + 256] = lo;
    }
}

// ---------------------------------------------------------------------------
// Kernel 2b: transpose g_f2cat [b][c][q] -> fp16 hi [b][q][256], pad q>=5440
// ---------------------------------------------------------------------------
__global__ __launch_bounds__(256) void bprep_kernel() {
    __shared__ float tile[32][33];
    int b = blockIdx.z, q0 = blockIdx.x * 32, c0 = blockIdx.y * 32;
    int tx = threadIdx.x, ty = threadIdx.y;
#pragma unroll
    for (int k = 0; k < 4; k++) {
        int c = c0 + ty + 8 * k, q = q0 + tx;
        tile[ty + 8 * k][tx] = (q < QTOT) ? g_f2cat[((size_t)b * Cc + c) * QTOT + q] : 0.f;
    }
    __syncthreads();
#pragma unroll
    for (int k = 0; k < 4; k++) {
        int q = q0 + ty + 8 * k, c = c0 + tx;
        g_Bh[((size_t)b * QPAD + q) * 256 + c] = __float2half_rn(tile[tx][ty + 8 * k]);
    }
}

// ---------------------------------------------------------------------------
// Kernel 3: HMMA GEMM. CTA 128(M) x 256(N), BK=64 halves, K'=512 (8 chunks),
// 256 threads / 8 warps (warp tile 64x64), 3-stage cp.async, 1 sync per chunk.
// grid (22, 32, 2).
// ---------------------------------------------------------------------------
#define GT 256
static constexpr int A_BYTES = 128 * 128;        // 16 KB
static constexpr int B_BYTES = 256 * 128;        // 32 KB
static constexpr int BUF_B = A_BYTES + B_BYTES;  // 48 KB
static constexpr int GEMM_SMEM = 3 * BUF_B;      // 144 KB

__global__ __launch_bounds__(GT, 1) void gemm_kernel() {
    extern __shared__ char smem[];
    const uint32_t sb = smem_to_u32(smem);
    const int tid = threadIdx.x, wid = tid >> 5, lid = tid & 31;
    const int b = blockIdx.z, m0 = blockIdx.y * 128, n0 = blockIdx.x * 256;
    const int warp_m = wid & 1, warp_n = wid >> 1;   // 2 x 4 warps, 64x64 each

    const __half* Ap = g_Ah + (size_t)b * PTOT * 512;
    const __half* Bp = g_Bh + (size_t)b * QPAD * 256;

    float acc[4][8][4];
#pragma unroll
    for (int i = 0; i < 4; i++)
#pragma unroll
        for (int j = 0; j < 8; j++)
#pragma unroll
            for (int k = 0; k < 4; k++) acc[i][j][k] = 0.f;

    // async load of chunk c (A k-off c*64, B k-off (c&3)*64) into buffer `buf`
    auto issue_loads = [&](int c, int buf) {
        int a_off = c * 64;
        int b_off = (c & 3) * 64;
        uint32_t aB = sb + buf * BUF_B;
        uint32_t bB = aB + A_BYTES;
#pragma unroll
        for (int i = 0; i < 12; i++) {
            int idx = tid + i * GT;               // 0..3071
            bool isB = idx >= 1024;
            int j = isB ? idx - 1024 : idx;
            int row = j >> 3, c16 = j & 7;
            const __half* src = isB
                ? Bp + (size_t)(n0 + row) * 256 + b_off + c16 * 8
                : Ap + (size_t)(m0 + row) * 512 + a_off + c16 * 8;
            uint32_t dst = (isB ? bB : aB) + SWZ((uint32_t)(row * 128 + c16 * 16));
            cp_async16(dst, src);
        }
        asm volatile("cp.async.commit_group;" ::: "memory");
    };

    issue_loads(0, 0);
    issue_loads(1, 1);

    const int a_row = warp_m * 64 + (lid & 15);
    const int a_kb  = (lid >> 4) * 16;
    const int b_row = warp_n * 64 + ((lid >> 4) & 1) * 8 + (lid & 7);
    const int b_kb  = ((lid >> 3) & 1) * 16;

    for (int c = 0; c < 8; c++) {
        if (c < 7) asm volatile("cp.async.wait_group 1;" ::: "memory");
        else       asm volatile("cp.async.wait_group 0;" ::: "memory");
        __syncthreads();              // chunk c resident; all warps left chunk c-1
        if (c < 6) issue_loads(c + 2, (c + 2) % 3);  // refills (c-1)%3: safe

        uint32_t aB = sb + (c % 3) * BUF_B;
        uint32_t bB = aB + A_BYTES;

#pragma unroll
        for (int ks = 0; ks < 4; ks++) {
            uint32_t af[4][4];
            uint32_t aAddr = aB + SWZ((uint32_t)(a_row * 128 + ks * 32 + a_kb));
#pragma unroll
            for (int mb = 0; mb < 4; mb++) ldsm_x4(af[mb], aAddr + mb * 2048);

            uint32_t bf[4][4];
            uint32_t bAddr = bB + SWZ((uint32_t)(b_row * 128 + ks * 32 + b_kb));
#pragma unroll
            for (int p = 0; p < 4; p++) ldsm_x4(bf[p], bAddr + p * 2048);

#pragma unroll
            for (int mb = 0; mb < 4; mb++)
#pragma unroll
                for (int nb = 0; nb < 8; nb++)
                    mma16816(acc[mb][nb], af[mb],
                             bf[nb >> 1][(nb & 1) * 2], bf[nb >> 1][(nb & 1) * 2 + 1]);
        }
    }

    // epilogue: scale 1/16, convert to fp16, store
    const float scale = 0.0625f;
    const int rbase = m0 + warp_m * 64 + (lid >> 2);
    const int cbase = n0 + warp_n * 64 + (lid & 3) * 2;
#pragma unroll
    for (int mb = 0; mb < 4; mb++) {
#pragma unroll
        for (int nb = 0; nb < 8; nb++) {
            int q = cbase + nb * 8;
            if (q < QTOT) {
                int r0 = rbase + mb * 16;
                __half* c0p = g_corrh + ((size_t)b * PTOT + r0) * QTOT + q;
                __half* c1p = c0p + (size_t)8 * QTOT;
                *(__half2*)c0p = __floats2half2_rn(acc[mb][nb][0] * scale,
                                                   acc[mb][nb][1] * scale);
                *(__half2*)c1p = __floats2half2_rn(acc[mb][nb][2] * scale,
                                                   acc[mb][nb][3] * scale);
            }
        }
    }
}

// ---------------------------------------------------------------------------
// Kernel 4: sampler, warp-per-query, fp16 corr. 128 threads = 4 queries.
// grid 16384.
// ---------------------------------------------------------------------------
__global__ __launch_bounds__(128) void sample_kernel(const float* __restrict__ coords,
                                                     float* __restrict__ out) {
    const int warp = threadIdx.x >> 5;
    const int lane = threadIdx.x & 31;
    const int qid = blockIdx.x * 4 + warp;      // (((b*8+n)*64+h)*64+w)
    const int w = qid & 63;
    const int h = (qid >> 6) & 63;
    const int n = (qid >> 12) & 7;
    const int b = qid >> 15;

    __shared__ float patch[4][10][16];
    float (*pp)[16] = patch[warp];

    const float cx = coords[((((size_t)b * NN + n) * 2 + 0) * HH + h) * WW + w];
    const float cy = coords[((((size_t)b * NN + n) * 2 + 1) * HH + h) * WW + w];

    const int p = h * WW + w;
    const __half* corrRow = g_corrh + ((size_t)b * PTOT + p) * QTOT;
    float* outBase = out + (size_t)qid * 324;

    const int   lvl_off[4] = {0, 4096, 5120, 5376};
    const int   wl[4]      = {64, 32, 16, 8};
    const float inv[4]     = {1.f, 0.5f, 0.25f, 0.125f};

#pragma unroll
    for (int lvl = 0; lvl < 4; lvl++) {
        const int   w2  = wl[lvl];
        const float wm1 = (float)(w2 - 1);
        const float cxs = cx * inv[lvl];
        const float cys = cy * inv[lvl];

        const float ylo = fminf(fmaxf(cys - 4.f, 0.f), wm1);
        const float yhi = fminf(fmaxf(cys + 4.f, 0.f), wm1);
        const float xlo = fminf(fmaxf(cxs - 4.f, 0.f), wm1);

        const int xstart = (int)floorf(xlo);
        const int ystart = (int)floorf(ylo);
        const int yend   = min((int)floorf(yhi) + 1, w2 - 1);
        const int xs4    = xstart & ~3;

        const __half* lbase = corrRow + lvl_off[lvl];

        if (lvl) __syncwarp();   // previous level's reads done before overwrite
        // 40 slots of 4 halves (8B) over 32 lanes
#pragma unroll
        for (int s = 0; s < 2; s++) {
            int slot = lane + s * 32;
            if (slot < 40) {
                int r = slot >> 2, cb = slot & 3;
                int col = xs4 + cb * 4;
                if (r <= yend - ystart && col < w2) {
                    uint2 v = *(const uint2*)(lbase + (ystart + r) * w2 + col);
                    float2 f0 = __half22float2(*(__half2*)&v.x);
                    float2 f1 = __half22float2(*(__half2*)&v.y);
                    pp[r][cb * 4 + 0] = f0.x;
                    pp[r][cb * 4 + 1] = f0.y;
                    pp[r][cb * 4 + 2] = f1.x;
                    pp[r][cb * 4 + 3] = f1.y;
                }
            }
        }
        __syncwarp();

#pragma unroll
        for (int s = 0; s < 3; s++) {
            int t = lane + s * 32;
            if (t < 81) {
                const int ix = t / 9;
                const int iy = t - ix * 9;
                float x = fminf(fmaxf(cxs + (float)(ix - 4), 0.f), wm1);
                float y = fminf(fmaxf(cys + (float)(iy - 4), 0.f), wm1);
                float x0f = floorf(x), y0f = floorf(y);
                float fx = x - x0f, fy = y - y0f;
                int x0 = (int)x0f;
                int y0 = (int)y0f;
                int x1 = min(x0 + 1, w2 - 1) - xs4;
                int y1 = min(y0 + 1, w2 - 1) - ystart;
                x0 -= xs4;
                y0 -= ystart;

                float v00 = pp[y0][x0], v01 = pp[y0][x1];
                float v10 = pp[y1][x0], v11 = pp[y1][x1];
                float v = v00 * (1.f - fy) * (1.f - fx)
                        + v01 * (1.f - fy) * fx
                        + v10 * fy * (1.f - fx)
                        + v11 * fy * fx;
                outBase[lvl * 81 + t] = v;
            }
        }
    }
}

// ---------------------------------------------------------------------------
// Launch
// ---------------------------------------------------------------------------
extern "C" void kernel_launch(void* const* d_in, const int* in_sizes, int n_in,
                              void* d_out, int out_size) {
    const float* f1     = (const float*)d_in[0];
    const float* f2     = (const float*)d_in[1];
    const float* coords = (const float*)d_in[2];
    float* out          = (float*)d_out;

    pool_kernel<<<dim3(Cc, Bb), 256>>>(f2);
    aprep_kernel<<<dim3(PTOT / 32, Cc / 32, Bb), dim3(32, 8)>>>(f1);
    bprep_kernel<<<dim3(QPAD / 32, Cc / 32, Bb), dim3(32, 8)>>>();

    cudaFuncSetAttribute(gemm_kernel, cudaFuncAttributeMaxDynamicSharedMemorySize, GEMM_SMEM);
    gemm_kernel<<<dim3(QPAD / 256, PTOT / 128, Bb), GT, GEMM_SMEM>>>();

    sample_kernel<<<Bb * NN * HH * WW / 4, 128>>>(coords, out);
}

// round 7
// speedup vs baseline: 4.1477x; 1.3484x over previous
#include <cuda_runtime.h>
#include <cuda_fp16.h>
#include <cstdint>

// ---------------------------------------------------------------------------
// CorrBlock: pooled-fmap2 fp16 HMMA GEMM (1-pass: Ahi*Bhi) + warp sampler.
// corr = (1/16) * f1^T f2cat ≈ (1/16)(Ahi*Bhi), fp32 acc, fp16 store.
// Calibrated error: ~3.6e-4 vs 1e-3 threshold.
// GEMM: CTA 128x256, 8 warps @ 64x64 warp tile, 3-stage cp.async, 1 sync/chunk.
// Round-6 fix: pipeline buffer index is (c+2)%3 (was c+2 -> SMEM OOB).
// ---------------------------------------------------------------------------

#define Bb 2
#define Cc 256
#define HH 64
#define WW 64
#define NN 8
#define QTOT 5440
#define QPAD 5632      // 22 N-tiles of 256
#define PTOT 4096      // H*W

// Scratch (no cudaMalloc allowed)
__device__ float g_f2cat[Bb * Cc * QTOT];                 // 11.1 MB
__device__ __half g_Ah[(size_t)Bb * PTOT * 256];          // 4.2 MB  [m][hi]
__device__ __half g_Bh[(size_t)Bb * QPAD * 256];          // 5.7 MB  [q][hi]
__device__ __half g_corrh[(size_t)Bb * PTOT * QTOT];      // 89 MB   fp16 corr

#define SWZ(o) ((o) ^ (((o) >> 3) & 0x70))

__device__ __forceinline__ uint32_t smem_to_u32(const void* p) {
    uint32_t a;
    asm("{ .reg .u64 t; cvta.to.shared.u64 t, %1; cvt.u32.u64 %0, t; }" : "=r"(a) : "l"(p));
    return a;
}
__device__ __forceinline__ void cp_async16(uint32_t dst, const void* src) {
    asm volatile("cp.async.cg.shared.global [%0], [%1], 16;" :: "r"(dst), "l"(src));
}
__device__ __forceinline__ void ldsm_x4(uint32_t* r, uint32_t addr) {
    asm volatile("ldmatrix.sync.aligned.m8n8.x4.shared.b16 {%0,%1,%2,%3}, [%4];"
                 : "=r"(r[0]), "=r"(r[1]), "=r"(r[2]), "=r"(r[3]) : "r"(addr));
}
__device__ __forceinline__ void mma16816(float* d, const uint32_t* a, uint32_t b0, uint32_t b1) {
    asm volatile("mma.sync.aligned.m16n8k16.row.col.f32.f16.f16.f32 "
                 "{%0,%1,%2,%3}, {%4,%5,%6,%7}, {%8,%9}, {%0,%1,%2,%3};"
                 : "+f"(d[0]), "+f"(d[1]), "+f"(d[2]), "+f"(d[3])
                 : "r"(a[0]), "r"(a[1]), "r"(a[2]), "r"(a[3]), "r"(b0), "r"(b1));
}

// ---------------------------------------------------------------------------
// Kernel 1: pool fmap2 into 4 levels, concatenated along q. grid (C, B), 256t.
// ---------------------------------------------------------------------------
__global__ __launch_bounds__(256) void pool_kernel(const float* __restrict__ f2) {
    int c = blockIdx.x, b = blockIdx.y;
    const float* in = f2 + ((size_t)b * Cc + c) * (HH * WW);
    float* outp = g_f2cat + ((size_t)b * Cc + c) * QTOT;
    __shared__ float s0[4096];
    __shared__ float s1[1024];
    __shared__ float s2[256];
    int tid = threadIdx.x;
    for (int i = tid; i < 1024; i += 256) {
        float4 v = ((const float4*)in)[i];
        ((float4*)s0)[i] = v;
        ((float4*)outp)[i] = v;
    }
    __syncthreads();
    for (int o = tid; o < 1024; o += 256) {
        int y = o >> 5, x = o & 31;
        float v = 0.25f * (s0[(2*y)*64 + 2*x] + s0[(2*y)*64 + 2*x + 1]
                         + s0[(2*y+1)*64 + 2*x] + s0[(2*y+1)*64 + 2*x + 1]);
        s1[o] = v; outp[4096 + o] = v;
    }
    __syncthreads();
    if (tid < 256) {
        int y = tid >> 4, x = tid & 15;
        float v = 0.25f * (s1[(2*y)*32 + 2*x] + s1[(2*y)*32 + 2*x + 1]
                         + s1[(2*y+1)*32 + 2*x] + s1[(2*y+1)*32 + 2*x + 1]);
        s2[tid] = v; outp[5120 + tid] = v;
    }
    __syncthreads();
    if (tid < 64) {
        int y = tid >> 3, x = tid & 7;
        float v = 0.25f * (s2[(2*y)*16 + 2*x] + s2[(2*y)*16 + 2*x + 1]
                         + s2[(2*y+1)*16 + 2*x] + s2[(2*y+1)*16 + 2*x + 1]);
        outp[5376 + tid] = v;
    }
}

// ---------------------------------------------------------------------------
// Kernel 2a: transpose f1 [b][c][p] -> fp16 hi [b][p][256]
// ---------------------------------------------------------------------------
__global__ __launch_bounds__(256) void aprep_kernel(const float* __restrict__ f1) {
    __shared__ float tile[32][33];
    int b = blockIdx.z, p0 = blockIdx.x * 32, c0 = blockIdx.y * 32;
    int tx = threadIdx.x, ty = threadIdx.y;
#pragma unroll
    for (int k = 0; k < 4; k++) {
        int c = c0 + ty + 8 * k;
        tile[ty + 8 * k][tx] = f1[((size_t)b * Cc + c) * PTOT + p0 + tx];
    }
    __syncthreads();
#pragma unroll
    for (int k = 0; k < 4; k++) {
        int p = p0 + ty + 8 * k, c = c0 + tx;
        g_Ah[((size_t)b * PTOT + p) * 256 + c] = __float2half_rn(tile[tx][ty + 8 * k]);
    }
}

// ---------------------------------------------------------------------------
// Kernel 2b: transpose g_f2cat [b][c][q] -> fp16 hi [b][q][256], pad q>=5440
// ---------------------------------------------------------------------------
__global__ __launch_bounds__(256) void bprep_kernel() {
    __shared__ float tile[32][33];
    int b = blockIdx.z, q0 = blockIdx.x * 32, c0 = blockIdx.y * 32;
    int tx = threadIdx.x, ty = threadIdx.y;
#pragma unroll
    for (int k = 0; k < 4; k++) {
        int c = c0 + ty + 8 * k, q = q0 + tx;
        tile[ty + 8 * k][tx] = (q < QTOT) ? g_f2cat[((size_t)b * Cc + c) * QTOT + q] : 0.f;
    }
    __syncthreads();
#pragma unroll
    for (int k = 0; k < 4; k++) {
        int q = q0 + ty + 8 * k, c = c0 + tx;
        g_Bh[((size_t)b * QPAD + q) * 256 + c] = __float2half_rn(tile[tx][ty + 8 * k]);
    }
}

// ---------------------------------------------------------------------------
// Kernel 3: HMMA GEMM. CTA 128(M) x 256(N), BK=64 halves, K'=256 (4 chunks),
// 256 threads / 8 warps (warp tile 64x64), 3-stage cp.async, 1 sync per chunk.
// grid (22, 32, 2).
// ---------------------------------------------------------------------------
#define GT 256
static constexpr int A_BYTES = 128 * 128;        // 16 KB
static constexpr int B_BYTES = 256 * 128;        // 32 KB
static constexpr int BUF_B = A_BYTES + B_BYTES;  // 48 KB
static constexpr int GEMM_SMEM = 3 * BUF_B;      // 144 KB

__global__ __launch_bounds__(GT, 1) void gemm_kernel() {
    extern __shared__ char smem[];
    const uint32_t sb = smem_to_u32(smem);
    const int tid = threadIdx.x, wid = tid >> 5, lid = tid & 31;
    const int b = blockIdx.z, m0 = blockIdx.y * 128, n0 = blockIdx.x * 256;
    const int warp_m = wid & 1, warp_n = wid >> 1;   // 2 x 4 warps, 64x64 each

    const __half* Ap = g_Ah + (size_t)b * PTOT * 256;
    const __half* Bp = g_Bh + (size_t)b * QPAD * 256;

    float acc[4][8][4];
#pragma unroll
    for (int i = 0; i < 4; i++)
#pragma unroll
        for (int j = 0; j < 8; j++)
#pragma unroll
            for (int k = 0; k < 4; k++) acc[i][j][k] = 0.f;

    // async load of chunk c (k-offset c*64) into buffer `buf` (0..2)
    auto issue_loads = [&](int c, int buf) {
        int k_off = c * 64;
        uint32_t aB = sb + buf * BUF_B;
        uint32_t bB = aB + A_BYTES;
#pragma unroll
        for (int i = 0; i < 12; i++) {
            int idx = tid + i * GT;               // 0..3071
            bool isB = idx >= 1024;
            int j = isB ? idx - 1024 : idx;
            int row = j >> 3, c16 = j & 7;
            const __half* src = isB
                ? Bp + (size_t)(n0 + row) * 256 + k_off + c16 * 8
                : Ap + (size_t)(m0 + row) * 256 + k_off + c16 * 8;
            uint32_t dst = (isB ? bB : aB) + SWZ((uint32_t)(row * 128 + c16 * 16));
            cp_async16(dst, src);
        }
        asm volatile("cp.async.commit_group;" ::: "memory");
    };

    issue_loads(0, 0);
    issue_loads(1, 1);

    const int a_row = warp_m * 64 + (lid & 15);
    const int a_kb  = (lid >> 4) * 16;
    const int b_row = warp_n * 64 + ((lid >> 4) & 1) * 8 + (lid & 7);
    const int b_kb  = ((lid >> 3) & 1) * 16;

    for (int c = 0; c < 4; c++) {
        if (c < 3) asm volatile("cp.async.wait_group 1;" ::: "memory");
        else       asm volatile("cp.async.wait_group 0;" ::: "memory");
        __syncthreads();              // chunk c resident; all warps left chunk c-1
        if (c < 2) issue_loads(c + 2, (c + 2) % 3);   // FIX: modulo buffer index

        uint32_t aB = sb + (c % 3) * BUF_B;
        uint32_t bB = aB + A_BYTES;

#pragma unroll
        for (int ks = 0; ks < 4; ks++) {
            uint32_t af[4][4];
            uint32_t aAddr = aB + SWZ((uint32_t)(a_row * 128 + ks * 32 + a_kb));
#pragma unroll
            for (int mb = 0; mb < 4; mb++) ldsm_x4(af[mb], aAddr + mb * 2048);

            uint32_t bf[4][4];
            uint32_t bAddr = bB + SWZ((uint32_t)(b_row * 128 + ks * 32 + b_kb));
#pragma unroll
            for (int p = 0; p < 4; p++) ldsm_x4(bf[p], bAddr + p * 2048);

#pragma unroll
            for (int mb = 0; mb < 4; mb++)
#pragma unroll
                for (int nb = 0; nb < 8; nb++)
                    mma16816(acc[mb][nb], af[mb],
                             bf[nb >> 1][(nb & 1) * 2], bf[nb >> 1][(nb & 1) * 2 + 1]);
        }
    }

    // epilogue: scale 1/16, convert to fp16, store
    const float scale = 0.0625f;
    const int rbase = m0 + warp_m * 64 + (lid >> 2);
    const int cbase = n0 + warp_n * 64 + (lid & 3) * 2;
#pragma unroll
    for (int mb = 0; mb < 4; mb++) {
#pragma unroll
        for (int nb = 0; nb < 8; nb++) {
            int q = cbase + nb * 8;
            if (q < QTOT) {
                int r0 = rbase + mb * 16;
                __half* c0p = g_corrh + ((size_t)b * PTOT + r0) * QTOT + q;
                __half* c1p = c0p + (size_t)8 * QTOT;
                *(__half2*)c0p = __floats2half2_rn(acc[mb][nb][0] * scale,
                                                   acc[mb][nb][1] * scale);
                *(__half2*)c1p = __floats2half2_rn(acc[mb][nb][2] * scale,
                                                   acc[mb][nb][3] * scale);
            }
        }
    }
}

// ---------------------------------------------------------------------------
// Kernel 4: sampler, warp-per-query, fp16 corr. 128 threads = 4 queries.
// grid 16384.
// ---------------------------------------------------------------------------
__global__ __launch_bounds__(128) void sample_kernel(const float* __restrict__ coords,
                                                     float* __restrict__ out) {
    const int warp = threadIdx.x >> 5;
    const int lane = threadIdx.x & 31;
    const int qid = blockIdx.x * 4 + warp;      // (((b*8+n)*64+h)*64+w)
    const int w = qid & 63;
    const int h = (qid >> 6) & 63;
    const int n = (qid >> 12) & 7;
    const int b = qid >> 15;

    __shared__ float patch[4][10][16];
    float (*pp)[16] = patch[warp];

    const float cx = coords[((((size_t)b * NN + n) * 2 + 0) * HH + h) * WW + w];
    const float cy = coords[((((size_t)b * NN + n) * 2 + 1) * HH + h) * WW + w];

    const int p = h * WW + w;
    const __half* corrRow = g_corrh + ((size_t)b * PTOT + p) * QTOT;
    float* outBase = out + (size_t)qid * 324;

    const int   lvl_off[4] = {0, 4096, 5120, 5376};
    const int   wl[4]      = {64, 32, 16, 8};
    const float inv[4]     = {1.f, 0.5f, 0.25f, 0.125f};

#pragma unroll
    for (int lvl = 0; lvl < 4; lvl++) {
        const int   w2  = wl[lvl];
        const float wm1 = (float)(w2 - 1);
        const float cxs = cx * inv[lvl];
        const float cys = cy * inv[lvl];

        const float ylo = fminf(fmaxf(cys - 4.f, 0.f), wm1);
        const float yhi = fminf(fmaxf(cys + 4.f, 0.f), wm1);
        const float xlo = fminf(fmaxf(cxs - 4.f, 0.f), wm1);

        const int xstart = (int)floorf(xlo);
        const int ystart = (int)floorf(ylo);
        const int yend   = min((int)floorf(yhi) + 1, w2 - 1);
        const int xs4    = xstart & ~3;

        const __half* lbase = corrRow + lvl_off[lvl];

        if (lvl) __syncwarp();   // previous level's reads done before overwrite
#pragma unroll
        for (int s = 0; s < 2; s++) {
            int slot = lane + s * 32;
            if (slot < 40) {
                int r = slot >> 2, cb = slot & 3;
                int col = xs4 + cb * 4;
                if (r <= yend - ystart && col < w2) {
                    uint2 v = *(const uint2*)(lbase + (ystart + r) * w2 + col);
                    float2 f0 = __half22float2(*(__half2*)&v.x);
                    float2 f1 = __half22float2(*(__half2*)&v.y);
                    pp[r][cb * 4 + 0] = f0.x;
                    pp[r][cb * 4 + 1] = f0.y;
                    pp[r][cb * 4 + 2] = f1.x;
                    pp[r][cb * 4 + 3] = f1.y;
                }
            }
        }
        __syncwarp();

#pragma unroll
        for (int s = 0; s < 3; s++) {
            int t = lane + s * 32;
            if (t < 81) {
                const int ix = t / 9;
                const int iy = t - ix * 9;
                float x = fminf(fmaxf(cxs + (float)(ix - 4), 0.f), wm1);
                float y = fminf(fmaxf(cys + (float)(iy - 4), 0.f), wm1);
                float x0f = floorf(x), y0f = floorf(y);
                float fx = x - x0f, fy = y - y0f;
                int x0 = (int)x0f;
                int y0 = (int)y0f;
                int x1 = min(x0 + 1, w2 - 1) - xs4;
                int y1 = min(y0 + 1, w2 - 1) - ystart;
                x0 -= xs4;
                y0 -= ystart;

                float v00 = pp[y0][x0], v01 = pp[y0][x1];
                float v10 = pp[y1][x0], v11 = pp[y1][x1];
                float v = v00 * (1.f - fy) * (1.f - fx)
                        + v01 * (1.f - fy) * fx
                        + v10 * fy * (1.f - fx)
                        + v11 * fy * fx;
                outBase[lvl * 81 + t] = v;
            }
        }
    }
}

// ---------------------------------------------------------------------------
// Launch
// ---------------------------------------------------------------------------
extern "C" void kernel_launch(void* const* d_in, const int* in_sizes, int n_in,
                              void* d_out, int out_size) {
    const float* f1     = (const float*)d_in[0];
    const float* f2     = (const float*)d_in[1];
    const float* coords = (const float*)d_in[2];
    float* out          = (float*)d_out;

    pool_kernel<<<dim3(Cc, Bb), 256>>>(f2);
    aprep_kernel<<<dim3(PTOT / 32, Cc / 32, Bb), dim3(32, 8)>>>(f1);
    bprep_kernel<<<dim3(QPAD / 32, Cc / 32, Bb), dim3(32, 8)>>>();

    cudaFuncSetAttribute(gemm_kernel, cudaFuncAttributeMaxDynamicSharedMemorySize, GEMM_SMEM);
    gemm_kernel<<<dim3(QPAD / 256, PTOT / 128, Bb), GT, GEMM_SMEM>>>();

    sample_kernel<<<Bb * NN * HH * WW / 4, 128>>>(coords, out);
}

// round 8
// speedup vs baseline: 4.4979x; 1.0844x over previous
#include <cuda_runtime.h>
#include <cuda_fp16.h>
#include <cstdint>

// ---------------------------------------------------------------------------
// CorrBlock: pooled-fmap2 fp16 HMMA GEMM (1-pass: Ahi*Bhi) + warp sampler.
// corr = (1/16) * f1^T f2cat ≈ (1/16)(Ahi*Bhi), fp32 acc, fp16 store.
// Round 8: GEMM CTA 128x128, 8 warps @ 32x64, 126-reg shape -> 2 CTAs/SM;
//          sampler prefetches all 4 pyramid levels before one syncwarp.
// ---------------------------------------------------------------------------

#define Bb 2
#define Cc 256
#define HH 64
#define WW 64
#define NN 8
#define QTOT 5440
#define QPAD 5632      // 44 N-tiles of 128
#define PTOT 4096      // H*W

// Scratch (no cudaMalloc allowed)
__device__ float g_f2cat[Bb * Cc * QTOT];                 // 11.1 MB
__device__ __half g_Ah[(size_t)Bb * PTOT * 256];          // 4.2 MB  [m][hi]
__device__ __half g_Bh[(size_t)Bb * QPAD * 256];          // 5.7 MB  [q][hi]
__device__ __half g_corrh[(size_t)Bb * PTOT * QTOT];      // 89 MB   fp16 corr

#define SWZ(o) ((o) ^ (((o) >> 3) & 0x70))

__device__ __forceinline__ uint32_t smem_to_u32(const void* p) {
    uint32_t a;
    asm("{ .reg .u64 t; cvta.to.shared.u64 t, %1; cvt.u32.u64 %0, t; }" : "=r"(a) : "l"(p));
    return a;
}
__device__ __forceinline__ void cp_async16(uint32_t dst, const void* src) {
    asm volatile("cp.async.cg.shared.global [%0], [%1], 16;" :: "r"(dst), "l"(src));
}
__device__ __forceinline__ void ldsm_x4(uint32_t* r, uint32_t addr) {
    asm volatile("ldmatrix.sync.aligned.m8n8.x4.shared.b16 {%0,%1,%2,%3}, [%4];"
                 : "=r"(r[0]), "=r"(r[1]), "=r"(r[2]), "=r"(r[3]) : "r"(addr));
}
__device__ __forceinline__ void mma16816(float* d, const uint32_t* a, uint32_t b0, uint32_t b1) {
    asm volatile("mma.sync.aligned.m16n8k16.row.col.f32.f16.f16.f32 "
                 "{%0,%1,%2,%3}, {%4,%5,%6,%7}, {%8,%9}, {%0,%1,%2,%3};"
                 : "+f"(d[0]), "+f"(d[1]), "+f"(d[2]), "+f"(d[3])
                 : "r"(a[0]), "r"(a[1]), "r"(a[2]), "r"(a[3]), "r"(b0), "r"(b1));
}

// ---------------------------------------------------------------------------
// Kernel 1: pool fmap2 into 4 levels, concatenated along q. grid (C, B), 256t.
// ---------------------------------------------------------------------------
__global__ __launch_bounds__(256) void pool_kernel(const float* __restrict__ f2) {
    int c = blockIdx.x, b = blockIdx.y;
    const float* in = f2 + ((size_t)b * Cc + c) * (HH * WW);
    float* outp = g_f2cat + ((size_t)b * Cc + c) * QTOT;
    __shared__ float s0[4096];
    __shared__ float s1[1024];
    __shared__ float s2[256];
    int tid = threadIdx.x;
    for (int i = tid; i < 1024; i += 256) {
        float4 v = ((const float4*)in)[i];
        ((float4*)s0)[i] = v;
        ((float4*)outp)[i] = v;
    }
    __syncthreads();
    for (int o = tid; o < 1024; o += 256) {
        int y = o >> 5, x = o & 31;
        float v = 0.25f * (s0[(2*y)*64 + 2*x] + s0[(2*y)*64 + 2*x + 1]
                         + s0[(2*y+1)*64 + 2*x] + s0[(2*y+1)*64 + 2*x + 1]);
        s1[o] = v; outp[4096 + o] = v;
    }
    __syncthreads();
    if (tid < 256) {
        int y = tid >> 4, x = tid & 15;
        float v = 0.25f * (s1[(2*y)*32 + 2*x] + s1[(2*y)*32 + 2*x + 1]
                         + s1[(2*y+1)*32 + 2*x] + s1[(2*y+1)*32 + 2*x + 1]);
        s2[tid] = v; outp[5120 + tid] = v;
    }
    __syncthreads();
    if (tid < 64) {
        int y = tid >> 3, x = tid & 7;
        float v = 0.25f * (s2[(2*y)*16 + 2*x] + s2[(2*y)*16 + 2*x + 1]
                         + s2[(2*y+1)*16 + 2*x] + s2[(2*y+1)*16 + 2*x + 1]);
        outp[5376 + tid] = v;
    }
}

// ---------------------------------------------------------------------------
// Kernel 2a: transpose f1 [b][c][p] -> fp16 hi [b][p][256]
// ---------------------------------------------------------------------------
__global__ __launch_bounds__(256) void aprep_kernel(const float* __restrict__ f1) {
    __shared__ float tile[32][33];
    int b = blockIdx.z, p0 = blockIdx.x * 32, c0 = blockIdx.y * 32;
    int tx = threadIdx.x, ty = threadIdx.y;
#pragma unroll
    for (int k = 0; k < 4; k++) {
        int c = c0 + ty + 8 * k;
        tile[ty + 8 * k][tx] = f1[((size_t)b * Cc + c) * PTOT + p0 + tx];
    }
    __syncthreads();
#pragma unroll
    for (int k = 0; k < 4; k++) {
        int p = p0 + ty + 8 * k, c = c0 + tx;
        g_Ah[((size_t)b * PTOT + p) * 256 + c] = __float2half_rn(tile[tx][ty + 8 * k]);
    }
}

// ---------------------------------------------------------------------------
// Kernel 2b: transpose g_f2cat [b][c][q] -> fp16 hi [b][q][256], pad q>=5440
// ---------------------------------------------------------------------------
__global__ __launch_bounds__(256) void bprep_kernel() {
    __shared__ float tile[32][33];
    int b = blockIdx.z, q0 = blockIdx.x * 32, c0 = blockIdx.y * 32;
    int tx = threadIdx.x, ty = threadIdx.y;
#pragma unroll
    for (int k = 0; k < 4; k++) {
        int c = c0 + ty + 8 * k, q = q0 + tx;
        tile[ty + 8 * k][tx] = (q < QTOT) ? g_f2cat[((size_t)b * Cc + c) * QTOT + q] : 0.f;
    }
    __syncthreads();
#pragma unroll
    for (int k = 0; k < 4; k++) {
        int q = q0 + ty + 8 * k, c = c0 + tx;
        g_Bh[((size_t)b * QPAD + q) * 256 + c] = __float2half_rn(tile[tx][ty + 8 * k]);
    }
}

// ---------------------------------------------------------------------------
// Kernel 3: HMMA GEMM. CTA 128(M) x 128(N), BK=64 halves, K'=256 (4 chunks),
// 256 threads / 8 warps (warp tile 32x64, acc 64 regs), 3-stage cp.async,
// __launch_bounds__(256,2) -> 2 CTAs/SM. grid (44, 32, 2).
// ---------------------------------------------------------------------------
#define GT 256
static constexpr int A_BYTES = 128 * 128;        // 16 KB
static constexpr int B_BYTES = 128 * 128;        // 16 KB
static constexpr int BUF_B = A_BYTES + B_BYTES;  // 32 KB
static constexpr int GEMM_SMEM = 3 * BUF_B;      // 96 KB

__global__ __launch_bounds__(GT, 2) void gemm_kernel() {
    extern __shared__ char smem[];
    const uint32_t sb = smem_to_u32(smem);
    const int tid = threadIdx.x, wid = tid >> 5, lid = tid & 31;
    const int b = blockIdx.z, m0 = blockIdx.y * 128, n0 = blockIdx.x * 128;
    const int warp_m = wid & 3, warp_n = wid >> 2;   // 4m x 2n warps, 32x64 each

    const __half* Ap = g_Ah + (size_t)b * PTOT * 256;
    const __half* Bp = g_Bh + (size_t)b * QPAD * 256;

    float acc[2][8][4];
#pragma unroll
    for (int i = 0; i < 2; i++)
#pragma unroll
        for (int j = 0; j < 8; j++)
#pragma unroll
            for (int k = 0; k < 4; k++) acc[i][j][k] = 0.f;

    // async load of chunk c (k-offset c*64) into buffer `buf` (0..2)
    auto issue_loads = [&](int c, int buf) {
        int k_off = c * 64;
        uint32_t aB = sb + buf * BUF_B;
        uint32_t bB = aB + A_BYTES;
#pragma unroll
        for (int i = 0; i < 8; i++) {
            int idx = tid + i * GT;               // 0..2047
            bool isB = idx >= 1024;
            int j = isB ? idx - 1024 : idx;
            int row = j >> 3, c16 = j & 7;
            const __half* src = isB
                ? Bp + (size_t)(n0 + row) * 256 + k_off + c16 * 8
                : Ap + (size_t)(m0 + row) * 256 + k_off + c16 * 8;
            uint32_t dst = (isB ? bB : aB) + SWZ((uint32_t)(row * 128 + c16 * 16));
            cp_async16(dst, src);
        }
        asm volatile("cp.async.commit_group;" ::: "memory");
    };

    issue_loads(0, 0);
    issue_loads(1, 1);

    const int a_row = warp_m * 32 + (lid & 15);
    const int a_kb  = (lid >> 4) * 16;
    const int b_row = warp_n * 64 + ((lid >> 4) & 1) * 8 + (lid & 7);
    const int b_kb  = ((lid >> 3) & 1) * 16;

    for (int c = 0; c < 4; c++) {
        if (c < 3) asm volatile("cp.async.wait_group 1;" ::: "memory");
        else       asm volatile("cp.async.wait_group 0;" ::: "memory");
        __syncthreads();              // chunk c resident; all warps left chunk c-1
        if (c < 2) issue_loads(c + 2, (c + 2) % 3);

        uint32_t aB = sb + (c % 3) * BUF_B;
        uint32_t bB = aB + A_BYTES;

#pragma unroll
        for (int ks = 0; ks < 4; ks++) {
            uint32_t af[2][4];
            uint32_t aAddr = aB + SWZ((uint32_t)(a_row * 128 + ks * 32 + a_kb));
            ldsm_x4(af[0], aAddr);
            ldsm_x4(af[1], aAddr + 2048);        // +16 rows

            uint32_t bf[4][4];
            uint32_t bAddr = bB + SWZ((uint32_t)(b_row * 128 + ks * 32 + b_kb));
#pragma unroll
            for (int p = 0; p < 4; p++) ldsm_x4(bf[p], bAddr + p * 2048);

#pragma unroll
            for (int mb = 0; mb < 2; mb++)
#pragma unroll
                for (int nb = 0; nb < 8; nb++)
                    mma16816(acc[mb][nb], af[mb],
                             bf[nb >> 1][(nb & 1) * 2], bf[nb >> 1][(nb & 1) * 2 + 1]);
        }
    }

    // epilogue: scale 1/16, convert to fp16, store
    const float scale = 0.0625f;
    const int rbase = m0 + warp_m * 32 + (lid >> 2);
    const int cbase = n0 + warp_n * 64 + (lid & 3) * 2;
#pragma unroll
    for (int mb = 0; mb < 2; mb++) {
#pragma unroll
        for (int nb = 0; nb < 8; nb++) {
            int q = cbase + nb * 8;
            if (q < QTOT) {
                int r0 = rbase + mb * 16;
                __half* c0p = g_corrh + ((size_t)b * PTOT + r0) * QTOT + q;
                __half* c1p = c0p + (size_t)8 * QTOT;
                *(__half2*)c0p = __floats2half2_rn(acc[mb][nb][0] * scale,
                                                   acc[mb][nb][1] * scale);
                *(__half2*)c1p = __floats2half2_rn(acc[mb][nb][2] * scale,
                                                   acc[mb][nb][3] * scale);
            }
        }
    }
}

// ---------------------------------------------------------------------------
// Kernel 4: sampler, warp-per-query, fp16 corr. All 4 levels prefetched
// before a single syncwarp (levels are mutually independent). grid 4096x128.
// ---------------------------------------------------------------------------
__global__ __launch_bounds__(128) void sample_kernel(const float* __restrict__ coords,
                                                     float* __restrict__ out) {
    const int warp = threadIdx.x >> 5;
    const int lane = threadIdx.x & 31;
    const int qid = blockIdx.x * 4 + warp;      // (((b*8+n)*64+h)*64+w)
    const int w = qid & 63;
    const int h = (qid >> 6) & 63;
    const int n = (qid >> 12) & 7;
    const int b = qid >> 15;

    __shared__ float patch[4][4][10][16];       // [warp][lvl][row][col]

    const float cx = coords[((((size_t)b * NN + n) * 2 + 0) * HH + h) * WW + w];
    const float cy = coords[((((size_t)b * NN + n) * 2 + 1) * HH + h) * WW + w];

    const int p = h * WW + w;
    const __half* corrRow = g_corrh + ((size_t)b * PTOT + p) * QTOT;
    float* outBase = out + (size_t)qid * 324;

    const int   lvl_off[4] = {0, 4096, 5120, 5376};
    const int   wl[4]      = {64, 32, 16, 8};
    const float inv[4]     = {1.f, 0.5f, 0.25f, 0.125f};

    float cxs_[4], cys_[4], wm1_[4];
    int   xs4_[4], yst_[4];

    // Phase 1: issue ALL levels' patch loads (independent -> MLP ~8/lane)
#pragma unroll
    for (int lvl = 0; lvl < 4; lvl++) {
        const int   w2  = wl[lvl];
        const float wm1 = (float)(w2 - 1);
        const float cxs = cx * inv[lvl];
        const float cys = cy * inv[lvl];
        const float ylo = fminf(fmaxf(cys - 4.f, 0.f), wm1);
        const float yhi = fminf(fmaxf(cys + 4.f, 0.f), wm1);
        const float xlo = fminf(fmaxf(cxs - 4.f, 0.f), wm1);
        const int xstart = (int)floorf(xlo);
        const int ystart = (int)floorf(ylo);
        const int yend   = min((int)floorf(yhi) + 1, w2 - 1);
        const int xs4    = xstart & ~3;

        cxs_[lvl] = cxs; cys_[lvl] = cys; wm1_[lvl] = wm1;
        xs4_[lvl] = xs4; yst_[lvl] = ystart;

        const __half* lbase = corrRow + lvl_off[lvl];
#pragma unroll
        for (int s = 0; s < 2; s++) {
            int slot = lane + s * 32;
            if (slot < 40) {
                int r = slot >> 2, cb = slot & 3;
                int col = xs4 + cb * 4;
                if (r <= yend - ystart && col < w2) {
                    uint2 v = *(const uint2*)(lbase + (ystart + r) * w2 + col);
                    float2 f0 = __half22float2(*(__half2*)&v.x);
                    float2 f1 = __half22float2(*(__half2*)&v.y);
                    patch[warp][lvl][r][cb * 4 + 0] = f0.x;
                    patch[warp][lvl][r][cb * 4 + 1] = f0.y;
                    patch[warp][lvl][r][cb * 4 + 2] = f1.x;
                    patch[warp][lvl][r][cb * 4 + 3] = f1.y;
                }
            }
        }
    }
    __syncwarp();

    // Phase 2: bilinear combine for all levels
#pragma unroll
    for (int lvl = 0; lvl < 4; lvl++) {
        const int   w2  = wl[lvl];
        const float wm1 = wm1_[lvl];
        const float cxs = cxs_[lvl];
        const float cys = cys_[lvl];
        const int   xs4 = xs4_[lvl];
        const int   yst = yst_[lvl];
        float (*pp)[16] = patch[warp][lvl];

#pragma unroll
        for (int s = 0; s < 3; s++) {
            int t = lane + s * 32;
            if (t < 81) {
                const int ix = t / 9;
                const int iy = t - ix * 9;
                float x = fminf(fmaxf(cxs + (float)(ix - 4), 0.f), wm1);
                float y = fminf(fmaxf(cys + (float)(iy - 4), 0.f), wm1);
                float x0f = floorf(x), y0f = floorf(y);
                float fx = x - x0f, fy = y - y0f;
                int x0 = (int)x0f;
                int y0 = (int)y0f;
                int x1 = min(x0 + 1, w2 - 1) - xs4;
                int y1 = min(y0 + 1, w2 - 1) - yst;
                x0 -= xs4;
                y0 -= yst;

                float v00 = pp[y0][x0], v01 = pp[y0][x1];
                float v10 = pp[y1][x0], v11 = pp[y1][x1];
                float v = v00 * (1.f - fy) * (1.f - fx)
                        + v01 * (1.f - fy) * fx
                        + v10 * fy * (1.f - fx)
                        + v11 * fy * fx;
                outBase[lvl * 81 + t] = v;
            }
        }
    }
}

// ---------------------------------------------------------------------------
// Launch
// ---------------------------------------------------------------------------
extern "C" void kernel_launch(void* const* d_in, const int* in_sizes, int n_in,
                              void* d_out, int out_size) {
    const float* f1     = (const float*)d_in[0];
    const float* f2     = (const float*)d_in[1];
    const float* coords = (const float*)d_in[2];
    float* out          = (float*)d_out;

    pool_kernel<<<dim3(Cc, Bb), 256>>>(f2);
    aprep_kernel<<<dim3(PTOT / 32, Cc / 32, Bb), dim3(32, 8)>>>(f1);
    bprep_kernel<<<dim3(QPAD / 32, Cc / 32, Bb), dim3(32, 8)>>>();

    cudaFuncSetAttribute(gemm_kernel, cudaFuncAttributeMaxDynamicSharedMemorySize, GEMM_SMEM);
    gemm_kernel<<<dim3(QPAD / 128, PTOT / 128, Bb), GT, GEMM_SMEM>>>();

    sample_kernel<<<Bb * NN * HH * WW / 4, 128>>>(coords, out);
}